// round 16
// baseline (speedup 1.0000x reference)
#include <cuda_runtime.h>
#include <cuda_bf16.h>
#include <cstdint>

// BS=64, G=64, L=100, D=64. NG=4096.
// softmax shift-invariance => attn = softmax_l(seqs[l].(W2@p)); lens/W1/W3/b unused.
// SINGLE mega-kernel: bids [0,2048) = attn CTAs (2 groups, R6 math, __ldcs streaming);
// bids [2048,2560) = MLP CTAs (8 rows, weights via LDG/L1-L2, flag-gated).
// Flags cleared by a tiny prior kernel each launch (graph-replay safe).

#define NG        4096
#define L         100
#define D         64
#define ATTN_CTAS (NG / 2)          // 2048
#define MLP_ROWS  8
#define MLP_CTAS  (NG / MLP_ROWS)   // 512
#define GRID      (ATTN_CTAS + MLP_CTAS)

typedef unsigned long long u64;

__device__ float g_weighted[NG * D];
__device__ int   g_flags[ATTN_CTAS];

// ---------------- helpers ----------------
__device__ __forceinline__ u64 pk2(float v) {
    u64 r; asm("mov.b64 %0, {%1, %1};" : "=l"(r) : "f"(v)); return r;
}
__device__ __forceinline__ void fma2(u64& d, u64 a, u64 b) {
    asm("fma.rn.f32x2 %0, %1, %2, %0;" : "+l"(d) : "l"(a), "l"(b));
}
__device__ __forceinline__ void add2(u64& d, u64 a) {
    asm("add.rn.f32x2 %0, %0, %1;" : "+l"(d) : "l"(a));
}
__device__ __forceinline__ float2 unpk(u64 v) {
    float2 r; asm("mov.b64 {%0, %1}, %2;" : "=f"(r.x), "=f"(r.y) : "l"(v)); return r;
}
__device__ __forceinline__ u64 pkpair(float lo, float hi) {
    u64 r; asm("mov.b64 %0, {%1, %2};" : "=l"(r) : "f"(lo), "f"(hi)); return r;
}

// ---------------------------------------------------------------------------
__global__ void clear_kernel() {
    int i = blockIdx.x * blockDim.x + threadIdx.x;
    if (i < ATTN_CTAS) g_flags[i] = 0;
}

// ---------------------------------------------------------------------------
// MLP stage: 8 rows, 4-way K-split (kh), 2 row-tiles (rt). Weights from GLOBAL
// (L1/L2-cached). Inputs from smem as duplicated u64. Reduction via P2/P1.
// ---------------------------------------------------------------------------
template<int K, bool BIAS, bool RELU, bool STOREH0, bool FINAL>
__device__ __forceinline__ void mstage(
    const u64* __restrict__ xin, int xs_,
    const float* __restrict__ Wg, const float* __restrict__ bias,
    u64* P1, u64* P2, u64* hdup, u64* h0p,
    float* __restrict__ gout, int growbase,
    int kh, int r0, int c0)
{
    u64 acc[4][2];
#pragma unroll
    for (int r = 0; r < 4; ++r) { acc[r][0] = 0ull; acc[r][1] = 0ull; }

    const int dbase = kh * (K / 4);
#pragma unroll
    for (int i = 0; i < K / 4; i += 2) {
        const int dd = dbase + i;
        float4 w0 = __ldg((const float4*)(Wg + (size_t)dd * 128 + c0));
        float4 w1 = __ldg((const float4*)(Wg + (size_t)(dd + 1) * 128 + c0));
        u64 w0l = *(const u64*)&w0.x, w0h = *(const u64*)&w0.z;
        u64 w1l = *(const u64*)&w1.x, w1h = *(const u64*)&w1.z;
#pragma unroll
        for (int r = 0; r < 4; ++r) {
            ulonglong2 xp = *(const ulonglong2*)&xin[(r0 + r) * xs_ + dd];
            fma2(acc[r][0], xp.x, w0l); fma2(acc[r][1], xp.x, w0h);
            fma2(acc[r][0], xp.y, w1l); fma2(acc[r][1], xp.y, w1h);
        }
    }

    if (kh >= 2) {
        u64* dst = P2 + (kh - 2) * 512;
#pragma unroll
        for (int r = 0; r < 4; ++r)
            *(ulonglong2*)&dst[(r0 + r) * 64 + (c0 >> 1)] =
                make_ulonglong2(acc[r][0], acc[r][1]);
    }
    __syncthreads();
    if (kh == 0) {
#pragma unroll
        for (int r = 0; r < 4; ++r) {
            ulonglong2 q = *(ulonglong2*)&P2[(r0 + r) * 64 + (c0 >> 1)];
            add2(acc[r][0], q.x); add2(acc[r][1], q.y);
        }
    }
    if (kh == 1) {
#pragma unroll
        for (int r = 0; r < 4; ++r) {
            ulonglong2 q = *(ulonglong2*)&P2[512 + (r0 + r) * 64 + (c0 >> 1)];
            add2(acc[r][0], q.x); add2(acc[r][1], q.y);
            *(ulonglong2*)&P1[(r0 + r) * 64 + (c0 >> 1)] =
                make_ulonglong2(acc[r][0], acc[r][1]);
        }
    }
    __syncthreads();
    if (kh == 0) {
        u64 bv0 = 0ull, bv1 = 0ull;
        if (BIAS) { bv0 = *(const u64*)&bias[c0]; bv1 = *(const u64*)&bias[c0 + 2]; }
#pragma unroll
        for (int r = 0; r < 4; ++r) {
            ulonglong2 q = *(ulonglong2*)&P1[(r0 + r) * 64 + (c0 >> 1)];
            add2(acc[r][0], q.x); add2(acc[r][1], q.y);
            if (BIAS) { add2(acc[r][0], bv0); add2(acc[r][1], bv1); }
            if (STOREH0)
                *(ulonglong2*)&h0p[(r0 + r) * 64 + (c0 >> 1)] =
                    make_ulonglong2(acc[r][0], acc[r][1]);
            float2 a = unpk(acc[r][0]), b = unpk(acc[r][1]);
            if (RELU) {
                a.x = fmaxf(a.x, 0.f); a.y = fmaxf(a.y, 0.f);
                b.x = fmaxf(b.x, 0.f); b.y = fmaxf(b.y, 0.f);
            }
            if (FINAL) {
                u64 o0 = pkpair(a.x, a.y), o1 = pkpair(b.x, b.y);
                ulonglong2 hp = *(ulonglong2*)&h0p[(r0 + r) * 64 + (c0 >> 1)];
                add2(o0, hp.x); add2(o1, hp.y);
                *(ulonglong2*)&gout[(size_t)(growbase + r0 + r) * 128 + c0] =
                    make_ulonglong2(o0, o1);
            } else {
                hdup[(r0 + r) * 128 + c0 + 0] = pk2(a.x);
                hdup[(r0 + r) * 128 + c0 + 1] = pk2(a.y);
                hdup[(r0 + r) * 128 + c0 + 2] = pk2(b.x);
                hdup[(r0 + r) * 128 + c0 + 3] = pk2(b.y);
            }
        }
    }
    __syncthreads();
}

// ---------------------------------------------------------------------------
__global__ __launch_bounds__(256) void mega_kernel(
    const float* __restrict__ seqs, const float* __restrict__ W2,
    const float* __restrict__ p,    const float* __restrict__ Wq,
    const float* __restrict__ Wl0,  const float* __restrict__ bl0,
    const float* __restrict__ Wl1,  const float* __restrict__ bl1,
    float* __restrict__ out)
{
    __shared__ char smraw[28672];
    const int bid = blockIdx.x;
    const int tid = threadIdx.x;

    if (bid < ATTN_CTAS) {
        // ======================= ATTENTION CTA =======================
        float* w2s   = (float*)smraw;               // [64][65]
        float* ps    = (float*)(smraw + 16640);     // [64]
        float* q_s   = (float*)(smraw + 16896);     // [64]
        float* ash   = (float*)(smraw + 17152);     // [2][104]
        float* red   = (float*)(smraw + 17984);     // [2][4]
        float* part4 = (float*)(smraw + 18016);     // [2][4][16][4]

        const int half = tid >> 7;
        const int t    = tid & 127;
        const int g    = bid * 2 + half;
        const int w    = t >> 5;
        const int lane = t & 31;
        const int c4   = t & 15;
        const int grp  = t >> 4;

        const float4* src = (const float4*)(seqs + (size_t)g * (L * D));
        float4 r[13];
#pragma unroll
        for (int k = 0; k < 13; ++k) {
            int idx = t + k * 128;
            if (idx < L * (D / 4)) r[k] = __ldcs(src + idx);   // streaming
            else                   r[k] = make_float4(0.f, 0.f, 0.f, 0.f);
        }

#pragma unroll
        for (int i = 0; i < 4; ++i) {
            int idx = tid + i * 256;
            float4 wv = __ldg((const float4*)W2 + idx);
            int row = idx >> 4, c = idx & 15;
            float* dst = &w2s[row * 65 + c * 4];
            dst[0] = wv.x; dst[1] = wv.y; dst[2] = wv.z; dst[3] = wv.w;
        }
        if (tid >= 64 && tid < 128) ps[tid - 64] = __ldg(p + tid - 64);
        __syncthreads();

        if (tid < D) {
            float acc = 0.f;
            const float* row = &w2s[tid * 65];
#pragma unroll 16
            for (int e = 0; e < D; ++e) acc += row[e] * ps[e];
            q_s[tid] = acc;
        }
        __syncthreads();

        const float4 q4 = *(const float4*)&q_s[c4 * 4];
#pragma unroll
        for (int k = 0; k < 13; ++k) {
            float v = r[k].x * q4.x + r[k].y * q4.y + r[k].z * q4.z + r[k].w * q4.w;
            v += __shfl_xor_sync(0xffffffffu, v, 1);
            v += __shfl_xor_sync(0xffffffffu, v, 2);
            v += __shfl_xor_sync(0xffffffffu, v, 4);
            v += __shfl_xor_sync(0xffffffffu, v, 8);
            int row = grp + 8 * k;
            if (c4 == 0 && row < L) ash[half * 104 + row] = v;
        }
        __syncthreads();

        float v = (t < L) ? ash[half * 104 + t] : -1e30f;
        float m = v;
#pragma unroll
        for (int o = 16; o > 0; o >>= 1) m = fmaxf(m, __shfl_xor_sync(0xffffffffu, m, o));
        if (lane == 0) red[half * 4 + w] = m;
        __syncthreads();
        float vmax = fmaxf(fmaxf(red[half * 4 + 0], red[half * 4 + 1]),
                           fmaxf(red[half * 4 + 2], red[half * 4 + 3]));
        __syncthreads();

        float e = (t < L) ? __expf(v - vmax) : 0.f;
        float sv = e;
#pragma unroll
        for (int o = 16; o > 0; o >>= 1) sv += __shfl_xor_sync(0xffffffffu, sv, o);
        if (lane == 0) red[half * 4 + w] = sv;
        __syncthreads();
        float inv = 1.f / (red[half * 4 + 0] + red[half * 4 + 1] +
                           red[half * 4 + 2] + red[half * 4 + 3]);
        if (t < L) ash[half * 104 + t] = e * inv;
        else if (t < 104) ash[half * 104 + t] = 0.f;
        __syncthreads();

        float4 p4 = make_float4(0.f, 0.f, 0.f, 0.f);
#pragma unroll
        for (int k = 0; k < 13; ++k) {
            float a = ash[half * 104 + grp + 8 * k];
            p4.x += a * r[k].x; p4.y += a * r[k].y;
            p4.z += a * r[k].z; p4.w += a * r[k].w;
        }
        p4.x += __shfl_xor_sync(0xffffffffu, p4.x, 16);
        p4.y += __shfl_xor_sync(0xffffffffu, p4.y, 16);
        p4.z += __shfl_xor_sync(0xffffffffu, p4.z, 16);
        p4.w += __shfl_xor_sync(0xffffffffu, p4.w, 16);
        if (lane < 16) *(float4*)&part4[((half * 4 + w) * 16 + lane) * 4] = p4;
        __syncthreads();
        if (t < D) {
            int ci = t >> 2, comp = t & 3;
            float sum = part4[((half * 4 + 0) * 16 + ci) * 4 + comp]
                      + part4[((half * 4 + 1) * 16 + ci) * 4 + comp]
                      + part4[((half * 4 + 2) * 16 + ci) * 4 + comp]
                      + part4[((half * 4 + 3) * 16 + ci) * 4 + comp];
            g_weighted[g * D + t] = sum;
        }
        __syncthreads();
        if (tid == 0) {
            __threadfence();
            *(volatile int*)&g_flags[bid] = 1;
        }
    } else {
        // ========================= MLP CTA =========================
        u64* xdup = (u64*)smraw;              // [8][64]
        u64* P1   = (u64*)(smraw + 4096);     // [8][64]
        u64* P2   = (u64*)(smraw + 8192);     // [2][8][64]
        u64* hdup = (u64*)(smraw + 16384);    // [8][128]
        u64* h0p  = (u64*)(smraw + 24576);    // [8][64]

        const int m = bid - ATTN_CTAS;        // 0..511, rows [8m, 8m+8)

        // wait for producers (attn CTAs 4m..4m+4)
        if (tid < 4) {
            volatile int* f = g_flags + 4 * m + tid;
            while (*f == 0) __nanosleep(128);
        }
        __syncthreads();
        __threadfence();                      // acquire: order data reads after flags

        // xdup: duplicated input rows
        {
            float2 xv = __ldg((const float2*)(g_weighted + (size_t)m * MLP_ROWS * D) + tid);
            xdup[2 * tid]     = pk2(xv.x);
            xdup[2 * tid + 1] = pk2(xv.y);
        }
        __syncthreads();

        const int wr   = tid >> 5;            // 0..7
        const int lane = tid & 31;
        const int rt   = wr & 1;              // row tile
        const int kh   = wr >> 1;             // K quarter
        const int r0   = rt * 4;
        const int c0   = lane * 4;

        // stage 1: h0 = X @ Wq (K=64); store h0pair + hdup
        mstage<64, false, false, true, false>(
            xdup, 64, Wq, nullptr, P1, P2, hdup, h0p, nullptr, 0, kh, r0, c0);
        // stage 2: h1 = relu(h0 @ Wl0 + bl0) -> hdup
        mstage<128, true, true, false, false>(
            hdup, 128, Wl0, bl0, P1, P2, hdup, h0p, nullptr, 0, kh, r0, c0);
        // stage 3: out = h0 + relu(h1 @ Wl1 + bl1)
        mstage<128, true, true, false, true>(
            hdup, 128, Wl1, bl1, P1, P2, hdup, h0p, out, m * MLP_ROWS, kh, r0, c0);
    }
}

// ---------------------------------------------------------------------------
extern "C" void kernel_launch(void* const* d_in, const int* in_sizes, int n_in,
                              void* d_out, int out_size) {
    const float* seqs = (const float*)d_in[0];
    const float* W2   = (const float*)d_in[3];
    const float* p    = (const float*)d_in[6];
    const float* Wq   = (const float*)d_in[7];
    const float* Wl0  = (const float*)d_in[8];
    const float* bl0  = (const float*)d_in[9];
    const float* Wl1  = (const float*)d_in[10];
    const float* bl1  = (const float*)d_in[11];
    float* out = (float*)d_out;

    clear_kernel<<<2, 1024>>>();
    mega_kernel<<<GRID, 256>>>(seqs, W2, p, Wq, Wl0, bl0, Wl1, bl1, out);
}

// round 17
// speedup vs baseline: 1.1449x; 1.1449x over previous
#include <cuda_runtime.h>
#include <cuda_bf16.h>
#include <cstdint>

// BS=64, G=64, L=100, D=64. NG=4096 groups.
// softmax shift-invariance: V_last/V_avg/b cancel => attn = softmax_l(seqs[l].(W2@p)).
// lens, W1, W3, b unused.
// attn: R6 (20.6us, DRAM-bound) + launch_dependents trigger.
// MLP: R10 (14.7us) launched with PDL; weights staged BEFORE griddepcontrol.wait.

#define NG   4096
#define L    100
#define D    64

typedef unsigned long long u64;

__device__ float g_weighted[NG * D];

// ---------------------------------------------------------------------------
// helpers
// ---------------------------------------------------------------------------
__device__ __forceinline__ void cp16(unsigned int s_addr, const void* g) {
    asm volatile("cp.async.cg.shared.global [%0], [%1], 16;\n" :: "r"(s_addr), "l"(g));
}
#define CP_COMMIT() asm volatile("cp.async.commit_group;\n" ::: "memory")
#define CP_WAIT(n)  asm volatile("cp.async.wait_group %0;\n" :: "n"(n) : "memory")

__device__ __forceinline__ u64 pk2(float v) {
    u64 r; asm("mov.b64 %0, {%1, %1};" : "=l"(r) : "f"(v)); return r;
}
__device__ __forceinline__ void fma2(u64& d, u64 a, u64 b) {
    asm("fma.rn.f32x2 %0, %1, %2, %0;" : "+l"(d) : "l"(a), "l"(b));
}
__device__ __forceinline__ float2 unpk(u64 v) {
    float2 r; asm("mov.b64 {%0, %1}, %2;" : "=f"(r.x), "=f"(r.y) : "l"(v)); return r;
}

// ---------------------------------------------------------------------------
// Kernel 1: attention pooling, 2 groups per block, 256 threads.
// ---------------------------------------------------------------------------
__global__ __launch_bounds__(256) void attn_kernel(
    const float* __restrict__ seqs, const float* __restrict__ W2,
    const float* __restrict__ p)
{
    __shared__ float w2s[D * 65];
    __shared__ float ps[D];
    __shared__ float q_s[D];
    __shared__ float attn_sh[2][104];
    __shared__ float red[2][4];
    __shared__ float part4[2][4][16][4];

    const int tid  = threadIdx.x;
    const int half = tid >> 7;
    const int t    = tid & 127;
    const int g    = blockIdx.x * 2 + half;
    const int w    = t >> 5;
    const int lane = t & 31;
    const int c4   = t & 15;
    const int grp  = t >> 4;

    const float4* src = (const float4*)(seqs + (size_t)g * (L * D));
    float4 r[13];
#pragma unroll
    for (int k = 0; k < 13; ++k) {
        int idx = t + k * 128;
        if (idx < L * (D / 4)) r[k] = __ldcs(src + idx);   // streaming: keep L1 clean
        else                   r[k] = make_float4(0.f, 0.f, 0.f, 0.f);
    }

#pragma unroll
    for (int i = 0; i < 4; ++i) {
        int idx = tid + i * 256;
        float4 wv = __ldg((const float4*)W2 + idx);
        int row = idx >> 4, c = idx & 15;
        float* dst = &w2s[row * 65 + c * 4];
        dst[0] = wv.x; dst[1] = wv.y; dst[2] = wv.z; dst[3] = wv.w;
    }
    if (tid >= 64 && tid < 128) ps[tid - 64] = __ldg(p + tid - 64);
    __syncthreads();

    if (tid < D) {
        float acc = 0.f;
        const float* row = &w2s[tid * 65];
#pragma unroll 16
        for (int e = 0; e < D; ++e) acc += row[e] * ps[e];
        q_s[tid] = acc;
    }
    __syncthreads();

    const float4 q4 = *(const float4*)&q_s[c4 * 4];
#pragma unroll
    for (int k = 0; k < 13; ++k) {
        float v = r[k].x * q4.x + r[k].y * q4.y + r[k].z * q4.z + r[k].w * q4.w;
        v += __shfl_xor_sync(0xffffffffu, v, 1);
        v += __shfl_xor_sync(0xffffffffu, v, 2);
        v += __shfl_xor_sync(0xffffffffu, v, 4);
        v += __shfl_xor_sync(0xffffffffu, v, 8);
        int row = grp + 8 * k;
        if (c4 == 0 && row < L) attn_sh[half][row] = v;
    }
    __syncthreads();

    float v = (t < L) ? attn_sh[half][t] : -1e30f;
    float m = v;
#pragma unroll
    for (int o = 16; o > 0; o >>= 1) m = fmaxf(m, __shfl_xor_sync(0xffffffffu, m, o));
    if (lane == 0) red[half][w] = m;
    __syncthreads();
    float vmax = fmaxf(fmaxf(red[half][0], red[half][1]),
                       fmaxf(red[half][2], red[half][3]));
    __syncthreads();

    float e = (t < L) ? __expf(v - vmax) : 0.f;
    float sv = e;
#pragma unroll
    for (int o = 16; o > 0; o >>= 1) sv += __shfl_xor_sync(0xffffffffu, sv, o);
    if (lane == 0) red[half][w] = sv;
    __syncthreads();
    float inv = 1.f / (red[half][0] + red[half][1] + red[half][2] + red[half][3]);
    if (t < L) attn_sh[half][t] = e * inv;
    else if (t < 104) attn_sh[half][t] = 0.f;
    __syncthreads();

    float4 p4 = make_float4(0.f, 0.f, 0.f, 0.f);
#pragma unroll
    for (int k = 0; k < 13; ++k) {
        float a = attn_sh[half][grp + 8 * k];
        p4.x += a * r[k].x; p4.y += a * r[k].y;
        p4.z += a * r[k].z; p4.w += a * r[k].w;
    }
    p4.x += __shfl_xor_sync(0xffffffffu, p4.x, 16);
    p4.y += __shfl_xor_sync(0xffffffffu, p4.y, 16);
    p4.z += __shfl_xor_sync(0xffffffffu, p4.z, 16);
    p4.w += __shfl_xor_sync(0xffffffffu, p4.w, 16);
    if (lane < 16) *(float4*)&part4[half][w][lane][0] = p4;
    __syncthreads();
    if (t < D) {
        int ci = t >> 2, comp = t & 3;
        float sum = part4[half][0][ci][comp] + part4[half][1][ci][comp]
                  + part4[half][2][ci][comp] + part4[half][3][ci][comp];
        g_weighted[g * D + t] = sum;
    }
    // allow dependent (MLP) CTAs to begin launching during the tail wave
    asm volatile("griddepcontrol.launch_dependents;" ::: "memory");
}

// ---------------------------------------------------------------------------
// MLP: 128 blocks x 512 threads, 32 rows/block. (R10 math, PDL prologue)
// warp wr: kh = wr>>3 (K-half), row tile r0 = (wr&7)*4; lane: c0 = lane*4.
// ---------------------------------------------------------------------------
template<int K, bool RELU, bool BIAS, bool RESID, bool GSTORE>
__device__ __forceinline__ void gemm_stage(
    const float* __restrict__ xb, const float* __restrict__ ws,
    const float* __restrict__ bias, const float* __restrict__ resid,
    float* __restrict__ obuf, float* __restrict__ part,
    int kh, int r0, int c0, int grow0)
{
    u64 acc[4][2];
#pragma unroll
    for (int i = 0; i < 4; ++i) { acc[i][0] = 0ull; acc[i][1] = 0ull; }

    const int dbase = kh * (K / 2);
#pragma unroll
    for (int i = 0; i < K / 2; i += 4) {
        const int dd = dbase + i;
        u64 b[4][2];
#pragma unroll
        for (int j = 0; j < 4; ++j) {
            float4 wv = *(const float4*)&ws[(dd + j) * 128 + c0];
            b[j][0] = *(const u64*)&wv.x;
            b[j][1] = *(const u64*)&wv.z;
        }
        float4 xv[4];
#pragma unroll
        for (int row = 0; row < 4; ++row)
            xv[row] = *(const float4*)&xb[(r0 + row) * K + dd];
#pragma unroll
        for (int j = 0; j < 4; ++j) {
#pragma unroll
            for (int row = 0; row < 4; ++row) {
                u64 x = pk2(((const float*)&xv[row])[j]);
                fma2(acc[row][0], x, b[j][0]);
                fma2(acc[row][1], x, b[j][1]);
            }
        }
    }

    if (kh) {
#pragma unroll
        for (int i = 0; i < 4; ++i) {
            float2 a = unpk(acc[i][0]), b2 = unpk(acc[i][1]);
            *(float4*)&part[(r0 + i) * 128 + c0] = make_float4(a.x, a.y, b2.x, b2.y);
        }
    }
    __syncthreads();
    if (!kh) {
        float4 bv = make_float4(0.f, 0.f, 0.f, 0.f);
        if (BIAS) bv = __ldg((const float4*)&bias[c0]);
#pragma unroll
        for (int i = 0; i < 4; ++i) {
            float4 pv = *(const float4*)&part[(r0 + i) * 128 + c0];
            float2 a = unpk(acc[i][0]), b2 = unpk(acc[i][1]);
            float4 o = make_float4(a.x + pv.x + bv.x, a.y + pv.y + bv.y,
                                   b2.x + pv.z + bv.z, b2.y + pv.w + bv.w);
            if (RELU) {
                o.x = fmaxf(o.x, 0.f); o.y = fmaxf(o.y, 0.f);
                o.z = fmaxf(o.z, 0.f); o.w = fmaxf(o.w, 0.f);
            }
            if (RESID) {
                const float* rr = &resid[(r0 + i) * 128 + c0];
                o.x += rr[0]; o.y += rr[1]; o.z += rr[2]; o.w += rr[3];
            }
            if (GSTORE)
                *(float4*)&obuf[(size_t)(grow0 + r0 + i) * 128 + c0] = o;
            else
                *(float4*)&obuf[(r0 + i) * 128 + c0] = o;
        }
    }
    __syncthreads();
}

__global__ __launch_bounds__(512) void mlp_kernel(
    const float* __restrict__ Wq,  const float* __restrict__ Wl0,
    const float* __restrict__ bl0, const float* __restrict__ Wl1,
    const float* __restrict__ bl1, float* __restrict__ out)
{
    extern __shared__ float smem[];
    float* sx   = smem;            // 32x64    =  2048 f
    float* sh0  = smem + 2048;     // 32x128   =  4096 f
    float* sh1  = smem + 6144;     // 32x128   =  4096 f
    float* part = smem + 10240;    // 32x128   =  4096 f
    float* wq   = smem + 14336;    // 64x128   =  8192 f
    float* wl0  = smem + 22528;    // 128x128  = 16384 f
    float* wl1  = smem + 38912;    // 128x128  = 16384 f  (55296 f = 216 KB)

    const int t    = threadIdx.x;
    const int row0 = blockIdx.x * 32;
    const unsigned int sb = (unsigned int)__cvta_generic_to_shared(smem);

    // ---- PDL prologue: stage ALL weights before waiting on attn ----
#pragma unroll
    for (int i = 0; i < 4; ++i) {
        int idx = t + i * 512;                             // 2048 f4
        cp16(sb + (14336 + idx * 4) * 4, (const float4*)Wq + idx);
    }
    CP_COMMIT();
#pragma unroll
    for (int i = 0; i < 8; ++i) {
        int idx = t + i * 512;                             // 4096 f4
        cp16(sb + (22528 + idx * 4) * 4, (const float4*)Wl0 + idx);
    }
    CP_COMMIT();
#pragma unroll
    for (int i = 0; i < 8; ++i) {
        int idx = t + i * 512;
        cp16(sb + (38912 + idx * 4) * 4, (const float4*)Wl1 + idx);
    }
    CP_COMMIT();

    // ---- wait for attn grid (g_weighted visible), then stage sx ----
    asm volatile("griddepcontrol.wait;" ::: "memory");
    cp16(sb + t * 16, (const float4*)(g_weighted + (size_t)row0 * D) + t);  // 512 f4
    CP_COMMIT();

    const int wr = t >> 5;            // warp 0..15
    const int kh = wr >> 3;           // K-half
    const int r0 = (wr & 7) * 4;      // rows [r0, r0+4)
    const int c0 = (t & 31) * 4;      // cols [c0, c0+4)

    // ---- stage 1: h0 = X @ Wq  (K=64) ----
    CP_WAIT(0);
    __syncthreads();
    gemm_stage<64, false, false, false, false>(sx, wq, nullptr, nullptr,
                                               sh0, part, kh, r0, c0, 0);

    // ---- stage 2: h1 = relu(h0 @ Wl0 + bl0) ----
    gemm_stage<128, true, true, false, false>(sh0, wl0, bl0, nullptr,
                                              sh1, part, kh, r0, c0, 0);

    // ---- stage 3: out = h0 + relu(h1 @ Wl1 + bl1) ----
    gemm_stage<128, true, true, true, true>(sh1, wl1, bl1, sh0,
                                            out, part, kh, r0, c0, row0);
}

// ---------------------------------------------------------------------------
extern "C" void kernel_launch(void* const* d_in, const int* in_sizes, int n_in,
                              void* d_out, int out_size) {
    const float* seqs = (const float*)d_in[0];
    const float* W2   = (const float*)d_in[3];
    const float* p    = (const float*)d_in[6];
    const float* Wq   = (const float*)d_in[7];
    const float* Wl0  = (const float*)d_in[8];
    const float* bl0  = (const float*)d_in[9];
    const float* Wl1  = (const float*)d_in[10];
    const float* bl1  = (const float*)d_in[11];
    float* out = (float*)d_out;

    static bool init_done = false;
    if (!init_done) {
        cudaFuncSetAttribute(mlp_kernel,
                             cudaFuncAttributeMaxDynamicSharedMemorySize, 221184);
        init_done = true;
    }

    attn_kernel<<<NG / 2, 256>>>(seqs, W2, p);

    // PDL launch: mlp may begin (and stage weights) while attn drains
    cudaLaunchConfig_t cfg = {};
    cfg.gridDim  = dim3(NG / 32);
    cfg.blockDim = dim3(512);
    cfg.dynamicSmemBytes = 221184;
    cfg.stream = 0;
    cudaLaunchAttribute attrs[1];
    attrs[0].id = cudaLaunchAttributeProgrammaticStreamSerialization;
    attrs[0].val.programmaticStreamSerializationAllowed = 1;
    cfg.attrs = attrs;
    cfg.numAttrs = 1;
    cudaLaunchKernelEx(&cfg, mlp_kernel, Wq, Wl0, bl0, Wl1, bl1, out);
}